// round 4
// baseline (speedup 1.0000x reference)
#include <cuda_runtime.h>

#define NN 512
#define DD 32
#define TT 8192
#define TWO_PI 6.2831853071795864769f

// ---- packed f32x2 helpers (sm_100+) ----
__device__ __forceinline__ unsigned long long ffma2(unsigned long long a,
                                                    unsigned long long b,
                                                    unsigned long long c) {
    unsigned long long d;
    asm("fma.rn.f32x2 %0, %1, %2, %3;" : "=l"(d) : "l"(a), "l"(b), "l"(c));
    return d;
}
__device__ __forceinline__ unsigned long long pack2(float lo, float hi) {
    unsigned long long r;
    asm("mov.b64 %0, {%1, %2};" : "=l"(r) : "f"(lo), "f"(hi));
    return r;
}
__device__ __forceinline__ void unpack2(unsigned long long v, float& lo, float& hi) {
    asm("mov.b64 {%0, %1}, %2;" : "=f"(lo), "=f"(hi) : "l"(v));
}

__global__ __launch_bounds__(NN, 1)
void rds_kernel(const float* __restrict__ Xr, const float* __restrict__ Xi,
                const float* __restrict__ tw, const float* __restrict__ Wr,
                const float* __restrict__ Wi, const float* __restrict__ phi0,
                const float* __restrict__ beta0, float* __restrict__ out) {
    const int tid  = threadIdx.x;          // neuron index
    const int lane = tid & 31;
    const int wid  = tid >> 5;

    // double-buffered per-step shared state
    __shared__ __align__(16) float4 xsA[2][DD];     // (xr,xr,xi,xi) per d
    __shared__ __align__(16) float  xsB[2][2 * DD]; // interleaved (xr,xi)
    __shared__ float  s_tgt[2];
    __shared__ __align__(16) float red[2][16];      // per-warp partial sums

    // W row resident in registers as packed (wr,wi)
    unsigned long long w2[DD];
#pragma unroll
    for (int d = 0; d < DD; d++)
        w2[d] = pack2(Wr[tid * DD + d], Wi[tid * DD + d]);

    float phi  = phi0[tid];
    float beta = beta0[tid];
    float lt   = 0.0f;
    float err  = 0.0f;   // redundant identical scalar chain in every thread

    float* outs   = out;
    float* betas  = out + TT;
    float* gammas = out + TT + (size_t)TT * NN;

    // prefetch step 0 inputs
    if (tid < DD) {
        float xr = Xr[tid], xi = Xi[tid];
        xsA[0][tid] = make_float4(xr, xr, xi, xi);
        xsB[0][2 * tid]     = xr;
        xsB[0][2 * tid + 1] = xi;
        if (tid == 0) s_tgt[0] = tw[0];
    }
    __syncthreads();

#pragma unroll 1
    for (int t = 0; t < TT; t++) {
        const int b = t & 1;

        float gamma = expf(-0.5f * beta);
        float dtl   = gamma * 1e-3f;
        lt += dtl;

        // ---- Z = W @ x  (complex matvec via FFMA2) ----
        unsigned long long accA = 0ull, accB = 0ull;  // (0,0) bit pattern
        const ulonglong2* xa = (const ulonglong2*)xsA[b];
#pragma unroll
        for (int d = 0; d < DD; d++) {
            ulonglong2 v = xa[d];                 // v.x=(xr,xr) v.y=(xi,xi)
            accA = ffma2(w2[d], v.x, accA);       // (Σwr·xr, Σwi·xr)
            accB = ffma2(w2[d], v.y, accB);       // (Σwr·xi, Σwi·xi)
        }
        float a1, a2, b1, b2;
        unpack2(accA, a1, a2);
        unpack2(accB, b1, b2);
        float zr = a1 - b2;
        float zi = b1 + a2;

        float theta = 10.0f * lt + phi;
        float sn, cs;
        sincosf(theta, &sn, &cs);
        // |Z| * relu(cos(theta - angle(Z))) == relu(cs*zr + sn*zi)
        float dot = cs * zr + sn * zi;
        float Y   = fmaxf(dot, 0.0f);
        float v   = Y * cs;                       // contribution to out

        // ---- block reduction: warp butterfly -> 16 partials ----
#pragma unroll
        for (int o = 16; o; o >>= 1)
            v += __shfl_xor_sync(0xffffffffu, v, o);
        if (lane == 0) red[b][wid] = v;

        // prefetch next step's x / tgt into the other buffer
        if (tid < DD && t + 1 < TT) {
            float xr = Xr[(t + 1) * DD + tid];
            float xi = Xi[(t + 1) * DD + tid];
            const int nb = b ^ 1;
            xsA[nb][tid] = make_float4(xr, xr, xi, xi);
            xsB[nb][2 * tid]     = xr;
            xsB[nb][2 * tid + 1] = xi;
            if (tid == 0) s_tgt[nb] = tw[t + 1];
        }
        float tgt = s_tgt[b];

        __syncthreads();   // the single per-step barrier

        // every thread sums the 16 partials in identical order (bitwise same)
        float4 r0 = *(const float4*)&red[b][0];
        float4 r1 = *(const float4*)&red[b][4];
        float4 r2 = *(const float4*)&red[b][8];
        float4 r3 = *(const float4*)&red[b][12];
        float out_v = (((r0.x + r0.y) + (r0.z + r0.w))
                    +  ((r1.x + r1.y) + (r1.z + r1.w)))
                    + (((r2.x + r2.y) + (r2.z + r2.w))
                    +  ((r3.x + r3.y) + (r3.z + r3.w)));

        // ---- scalar thermodynamic feedback (identical in all threads) ----
        err = 0.99f * err + 0.01f * fabsf(tgt - out_v);
        float rel  = __fdividef(err, fabsf(tgt) + 0.01f);
        float btgt = 3.5f * expf(-5.0f * rel);
        // btgt > beta: tau = 0.5/(gamma+1e-6) -> DT/tau = 2e-3*(gamma+1e-6)
        float a_s  = (btgt > beta)
                   ? (1.0f - expf(-2e-3f * (gamma + 1e-6f)))
                   : (1.0f - expf(-(1e-3f / 0.03f)));
        float bnew = beta + a_s * (btgt - beta);
        bnew = fminf(fmaxf(bnew, 0.005f), 5.0f);

        // ---- W update: w += (0.05*Y*x - bnew*Y^2*w) * dtl ----
        float gg = 0.05f * Y * dtl;
        float ddc = bnew * Y * Y * dtl;
        unsigned long long g2  = pack2(gg, gg);
        unsigned long long nd2 = pack2(-ddc, -ddc);
        const ulonglong2* xb = (const ulonglong2*)xsB[b];
#pragma unroll
        for (int j = 0; j < DD / 2; j++) {
            ulonglong2 u = xb[j];                 // u.x=(xr0,xi0) u.y=(xr1,xi1)
            w2[2 * j]     = ffma2(g2, u.x, ffma2(nd2, w2[2 * j],     w2[2 * j]));
            w2[2 * j + 1] = ffma2(g2, u.y, ffma2(nd2, w2[2 * j + 1], w2[2 * j + 1]));
        }

        // ---- phase pull + wrap (jnp.mod semantics) ----
        float dphi = (2.0f / 512.0f) * (-tgt * sn) * dtl;
        phi += dphi;
        phi -= floorf(phi * (1.0f / TWO_PI)) * TWO_PI;

        // ---- outputs ----
        betas[t * NN + tid]  = bnew;
        gammas[t * NN + tid] = gamma;
        if (tid == 0) outs[t] = out_v;

        beta = bnew;
    }
}

extern "C" void kernel_launch(void* const* d_in, const int* in_sizes, int n_in,
                              void* d_out, int out_size) {
    const float* Xr    = (const float*)d_in[0];
    const float* Xi    = (const float*)d_in[1];
    const float* tw    = (const float*)d_in[2];
    const float* Wr    = (const float*)d_in[3];
    const float* Wi    = (const float*)d_in[4];
    const float* phi0  = (const float*)d_in[5];
    const float* beta0 = (const float*)d_in[6];
    float* out = (float*)d_out;
    rds_kernel<<<1, NN>>>(Xr, Xi, tw, Wr, Wi, phi0, beta0, out);
}

// round 5
// speedup vs baseline: 1.0568x; 1.0568x over previous
#include <cuda_runtime.h>

#define NN 512
#define DD 32
#define TT 8192
#define TWO_PI 6.2831853071795864769f
#define INV_TWO_PI 0.15915494309189535f

// ---- packed f32x2 helpers (sm_100+) ----
__device__ __forceinline__ unsigned long long ffma2(unsigned long long a,
                                                    unsigned long long b,
                                                    unsigned long long c) {
    unsigned long long d;
    asm("fma.rn.f32x2 %0, %1, %2, %3;" : "=l"(d) : "l"(a), "l"(b), "l"(c));
    return d;
}
__device__ __forceinline__ unsigned long long pack2(float lo, float hi) {
    unsigned long long r;
    asm("mov.b64 %0, {%1, %2};" : "=l"(r) : "f"(lo), "f"(hi));
    return r;
}
__device__ __forceinline__ void unpack2(unsigned long long v, float& lo, float& hi) {
    asm("mov.b64 {%0, %1}, %2;" : "=f"(lo), "=f"(hi) : "l"(v));
}
__device__ __forceinline__ float wrap2pi(float x) {
    return x - floorf(x * INV_TWO_PI) * TWO_PI;
}

__global__ __launch_bounds__(NN, 1)
void rds_kernel(const float* __restrict__ Xr, const float* __restrict__ Xi,
                const float* __restrict__ tw, const float* __restrict__ Wr,
                const float* __restrict__ Wi, const float* __restrict__ phi0,
                const float* __restrict__ beta0, float* __restrict__ out) {
    const int tid  = threadIdx.x;          // neuron index
    const int lane = tid & 31;
    const int wid  = tid >> 5;

    // double-buffered per-step shared state
    __shared__ __align__(16) float4 xsA[2][DD];     // (xr,xr,xi,xi) per d
    __shared__ __align__(16) float  xsB[2][2 * DD]; // interleaved (xr,xi)
    __shared__ float  s_tgt[2];
    __shared__ __align__(16) float red[2][16];      // per-warp partial sums

    // W row resident in registers as packed (wr,wi)
    unsigned long long w2[DD];
#pragma unroll
    for (int d = 0; d < DD; d++)
        w2[d] = pack2(Wr[tid * DD + d], Wi[tid * DD + d]);

    float phi  = phi0[tid];
    float beta = beta0[tid];
    float lt   = 0.0f;
    float err  = 0.0f;   // redundant identical scalar chain in every thread

    float* outs   = out;
    float* betas  = out + TT;
    float* gammas = out + TT + (size_t)TT * NN;

    // prefetch step 0 inputs
    if (tid < DD) {
        float xr = Xr[tid], xi = Xi[tid];
        xsA[0][tid] = make_float4(xr, xr, xi, xi);
        xsB[0][2 * tid]     = xr;
        xsB[0][2 * tid + 1] = xi;
        if (tid == 0) s_tgt[0] = tw[0];
    }

    // ---- software-pipelined head: gamma/lt/theta/sincos for step 0 ----
    float gamma = __expf(-0.5f * beta);
    float dtl   = gamma * 1e-3f;
    lt += dtl;
    float sn, cs;
    __sincosf(wrap2pi(10.0f * lt + phi), &sn, &cs);

    __syncthreads();

#pragma unroll 1
    for (int t = 0; t < TT; t++) {
        const int b = t & 1;

        // ---- Z = W @ x  (complex matvec via FFMA2) ----
        unsigned long long accA = 0ull, accB = 0ull;  // (0,0) bit pattern
        const ulonglong2* xa = (const ulonglong2*)xsA[b];
#pragma unroll
        for (int d = 0; d < DD; d++) {
            ulonglong2 v = xa[d];                 // v.x=(xr,xr) v.y=(xi,xi)
            accA = ffma2(w2[d], v.x, accA);       // (Σwr·xr, Σwi·xr)
            accB = ffma2(w2[d], v.y, accB);       // (Σwr·xi, Σwi·xi)
        }
        float a1, a2, b1, b2;
        unpack2(accA, a1, a2);
        unpack2(accB, b1, b2);
        float zr = a1 - b2;
        float zi = b1 + a2;

        // |Z| * relu(cos(theta - angle(Z))) == relu(cs*zr + sn*zi)
        float dot = cs * zr + sn * zi;
        float Y   = fmaxf(dot, 0.0f);
        float v   = Y * cs;                       // contribution to out

        // ---- block reduction: warp butterfly -> 16 partials ----
#pragma unroll
        for (int o = 16; o; o >>= 1)
            v += __shfl_xor_sync(0xffffffffu, v, o);
        if (lane == 0) red[b][wid] = v;

        // prefetch next step's x / tgt into the other buffer
        if (tid < DD && t + 1 < TT) {
            float xr = Xr[(t + 1) * DD + tid];
            float xi = Xi[(t + 1) * DD + tid];
            const int nb = b ^ 1;
            xsA[nb][tid] = make_float4(xr, xr, xi, xi);
            xsB[nb][2 * tid]     = xr;
            xsB[nb][2 * tid + 1] = xi;
            if (tid == 0) s_tgt[nb] = tw[t + 1];
        }
        float tgt = s_tgt[b];

        __syncthreads();   // the single per-step barrier

        // every thread sums the 16 partials in identical order (bitwise same)
        float4 r0 = *(const float4*)&red[b][0];
        float4 r1 = *(const float4*)&red[b][4];
        float4 r2 = *(const float4*)&red[b][8];
        float4 r3 = *(const float4*)&red[b][12];
        float out_v = (((r0.x + r0.y) + (r0.z + r0.w))
                    +  ((r1.x + r1.y) + (r1.z + r1.w)))
                    + (((r2.x + r2.y) + (r2.z + r2.w))
                    +  ((r3.x + r3.y) + (r3.z + r3.w)));

        // ---- scalar thermodynamic feedback (identical in all threads) ----
        err = 0.99f * err + 0.01f * fabsf(tgt - out_v);
        float rel  = __fdividef(err, fabsf(tgt) + 0.01f);
        float btgt = 3.5f * __expf(-5.0f * rel);
        // btgt > beta: tau = 0.5/(gamma+1e-6) -> DT/tau = 2e-3*(gamma+1e-6)
        // else: a_s = 1 - exp(-DT/0.03) = constant
        float a_s  = (btgt > beta)
                   ? (1.0f - __expf(-2e-3f * (gamma + 1e-6f)))
                   : 0.03278394f;
        float bnew = beta + a_s * (btgt - beta);
        bnew = fminf(fmaxf(bnew, 0.005f), 5.0f);

        // ---- outputs ----
        betas[t * NN + tid]  = bnew;
        gammas[t * NN + tid] = gamma;
        if (tid == 0) outs[t] = out_v;

        // ---- phase pull + wrap (jnp.mod semantics) ----
        float dphi = (2.0f / 512.0f) * (-tgt * sn) * dtl;
        float phin = phi + dphi;
        phin -= floorf(phin * INV_TWO_PI) * TWO_PI;

        // ---- W-update scale factors for THIS step (need Y, bnew, dtl) ----
        float gg  = 0.05f * Y * dtl;
        float ddc = bnew * Y * Y * dtl;

        // ---- pipelined head of NEXT step: gamma'/lt'/theta'/sincos' ----
        // (issued before the FFMA2 block so MUFU latency hides under it)
        float gamman = __expf(-0.5f * bnew);
        float dtln   = gamman * 1e-3f;
        float ltn    = lt + dtln;
        float snn, csn;
        __sincosf(wrap2pi(10.0f * ltn + phin), &snn, &csn);

        // ---- W update: w += (0.05*Y*x - bnew*Y^2*w) * dtl ----
        unsigned long long g2  = pack2(gg, gg);
        unsigned long long nd2 = pack2(-ddc, -ddc);
        const ulonglong2* xb = (const ulonglong2*)xsB[b];
#pragma unroll
        for (int j = 0; j < DD / 2; j++) {
            ulonglong2 u = xb[j];                 // u.x=(xr0,xi0) u.y=(xr1,xi1)
            w2[2 * j]     = ffma2(g2, u.x, ffma2(nd2, w2[2 * j],     w2[2 * j]));
            w2[2 * j + 1] = ffma2(g2, u.y, ffma2(nd2, w2[2 * j + 1], w2[2 * j + 1]));
        }

        // rotate pipelined state
        beta  = bnew;
        phi   = phin;
        gamma = gamman;
        dtl   = dtln;
        lt    = ltn;
        sn    = snn;
        cs    = csn;
    }
}

extern "C" void kernel_launch(void* const* d_in, const int* in_sizes, int n_in,
                              void* d_out, int out_size) {
    const float* Xr    = (const float*)d_in[0];
    const float* Xi    = (const float*)d_in[1];
    const float* tw    = (const float*)d_in[2];
    const float* Wr    = (const float*)d_in[3];
    const float* Wi    = (const float*)d_in[4];
    const float* phi0  = (const float*)d_in[5];
    const float* beta0 = (const float*)d_in[6];
    float* out = (float*)d_out;
    rds_kernel<<<1, NN>>>(Xr, Xi, tw, Wr, Wi, phi0, beta0, out);
}